// round 8
// baseline (speedup 1.0000x reference)
#include <cuda_runtime.h>

#define NB   32
#define CC   512
#define LL   512
#define KG   10
#define VK   8

// Scratch (no allocations allowed)
__device__ float g_a   [NB * LL * VK];        // softmax assignments [n][l][k], k<8
__device__ float g_asum[NB * 8 * VK];         // per-l-tile assign_sum partials
__device__ float g_axp [NB * VK * CC];        // assign_x [n][k][c]
__device__ int   g_ctr [NB];                  // arrival counters (zero-init, self-resetting)

typedef unsigned long long u64;

__device__ __forceinline__ u64 pack2(float lo, float hi) {
    u64 r; asm("mov.b64 %0,{%1,%2};" : "=l"(r) : "f"(lo), "f"(hi)); return r;
}
__device__ __forceinline__ void unpack2(u64 v, float& lo, float& hi) {
    asm("mov.b64 {%0,%1},%2;" : "=f"(lo), "=f"(hi) : "l"(v));
}
__device__ __forceinline__ u64 ffma2(u64 a, u64 b, u64 c) {
    u64 d; asm("fma.rn.f32x2 %0,%1,%2,%3;" : "=l"(d) : "l"(a), "l"(b), "l"(c)); return d;
}

// ---------------------------------------------------------------------------
// KA: logits + softmax + a + assign_sum partials, fused.
// grid (L/64, N), block 256. Warp w owns c-slice [64w, 64w+64) for the
// block's 64 l's (thread = l-pair). Cross-warp combine in smem, then
// 64 threads finish softmax; writes a in [l][k] layout (2x float4/thread).
// ---------------------------------------------------------------------------
__global__ __launch_bounds__(256) void ka_logits_softmax(
    const float* __restrict__ x, const float* __restrict__ w,
    const float* __restrict__ b)
{
    __shared__ float wsh[CC * 12];        // 24 KB, [c][k] 12-padded
    __shared__ float psh[8 * KG * 64];    // 20 KB, [warp][k][l_local]
    __shared__ float red[2][VK];

    const int tid   = threadIdx.x;
    const int lane  = tid & 31;
    const int warp  = tid >> 5;
    const int n     = blockIdx.y;
    const int lbase = blockIdx.x * 64;

    for (int i = tid; i < KG * CC; i += 256) {
        int k = i >> 9, c = i & (CC - 1);
        wsh[c * 12 + k] = w[i];
    }
    __syncthreads();

    u64 accA[5], accB[5];
#pragma unroll
    for (int p = 0; p < 5; p++) { accA[p] = 0ull; accB[p] = 0ull; }

    const int c0 = warp * 64;
    const float* xp = x + ((size_t)n * CC + c0) * LL + lbase + lane * 2;
#pragma unroll 1
    for (int cb = 0; cb < 64; cb += 16) {
        const float* xc = xp + (size_t)cb * LL;
        float2 xv[16];
#pragma unroll
        for (int i = 0; i < 16; i++) xv[i] = *(const float2*)(xc + i * LL);
#pragma unroll
        for (int i = 0; i < 16; i++) {
            u64 xa = pack2(xv[i].x, xv[i].x);
            u64 xb = pack2(xv[i].y, xv[i].y);
            const float* wr = wsh + (c0 + cb + i) * 12;
            u64 w0 = *(const u64*)(wr + 0);
            u64 w1 = *(const u64*)(wr + 2);
            u64 w2 = *(const u64*)(wr + 4);
            u64 w3 = *(const u64*)(wr + 6);
            u64 w4 = *(const u64*)(wr + 8);
            accA[0] = ffma2(w0, xa, accA[0]);  accB[0] = ffma2(w0, xb, accB[0]);
            accA[1] = ffma2(w1, xa, accA[1]);  accB[1] = ffma2(w1, xb, accB[1]);
            accA[2] = ffma2(w2, xa, accA[2]);  accB[2] = ffma2(w2, xb, accB[2]);
            accA[3] = ffma2(w3, xa, accA[3]);  accB[3] = ffma2(w3, xb, accB[3]);
            accA[4] = ffma2(w4, xa, accA[4]);  accB[4] = ffma2(w4, xb, accB[4]);
        }
    }

    // stash this warp's partial logits: psh[warp][k][l_local]
    {
        float lgA[KG], lgB[KG];
#pragma unroll
        for (int p = 0; p < 5; p++) {
            unpack2(accA[p], lgA[2 * p], lgA[2 * p + 1]);
            unpack2(accB[p], lgB[2 * p], lgB[2 * p + 1]);
        }
        float* pr = psh + (warp * KG) * 64 + lane * 2;
#pragma unroll
        for (int k = 0; k < KG; k++) {
            float2 v; v.x = lgA[k]; v.y = lgB[k];
            *(float2*)(pr + k * 64) = v;
        }
    }
    __syncthreads();

    // 64 threads (warps 0-1) finish: combine 8 warps, softmax, write a + asum
    if (tid < 64) {
        float lg[KG];
#pragma unroll
        for (int k = 0; k < KG; k++) lg[k] = __ldg(b + k);
#pragma unroll
        for (int wp = 0; wp < 8; wp++) {
            const float* pr = psh + (wp * KG) * 64 + tid;
#pragma unroll
            for (int k = 0; k < KG; k++) lg[k] += pr[k * 64];
        }

        float m = lg[0];
#pragma unroll
        for (int k = 1; k < KG; k++) m = fmaxf(m, lg[k]);
        float s = 0.f;
#pragma unroll
        for (int k = 0; k < KG; k++) { lg[k] = __expf(lg[k] - m); s += lg[k]; }
        float inv = 1.f / s;

#pragma unroll
        for (int k = 0; k < VK; k++) lg[k] *= inv;

        // a in [n][l][k] layout: two coalesced float4 stores
        float* ap = g_a + ((size_t)n * LL + lbase + tid) * VK;
        *(float4*)(ap)     = make_float4(lg[0], lg[1], lg[2], lg[3]);
        *(float4*)(ap + 4) = make_float4(lg[4], lg[5], lg[6], lg[7]);

        // octet reduce-scatter: lane ends with sum over its warp of lg[lane&7]
#pragma unroll
        for (int o = 4; o >= 1; o >>= 1) {
            bool up = (lane & o) != 0;
#pragma unroll
            for (int i = 0; i < 8; i++) {
                if (i < o) {
                    float keep = up ? lg[i + o] : lg[i];
                    float send = up ? lg[i] : lg[i + o];
                    lg[i] = keep + __shfl_xor_sync(0xffffffffu, send, o);
                }
            }
        }
        float t0 = lg[0];
        t0 += __shfl_xor_sync(0xffffffffu, t0, 8);
        t0 += __shfl_xor_sync(0xffffffffu, t0, 16);
        if (lane < 8) red[warp][lane] = t0;
    }
    __syncthreads();
    if (tid < VK)
        g_asum[((size_t)n * 8 + blockIdx.x) * VK + tid] = red[0][tid] + red[1][tid];
}

// ---------------------------------------------------------------------------
// KB: assign_x + (last block per n) full epilogue.
// grid (C/32, N), block 256, 4 CTAs/SM. Warp owns 4 c over all 512 l.
// a-tile padded to 12 floats/row: each l's 8 a-values = 2x LDS.128
// (conflict-free in 8-lane phases). acc = 16 u64 (k-pair packed).
// Epilogue residuals staged through ash to keep the cold path reg-light.
// ---------------------------------------------------------------------------
__global__ __launch_bounds__(256, 4) void kb_assign_epilogue(
    const float* __restrict__ x, const float* __restrict__ centers,
    float* __restrict__ out)
{
    __shared__ __align__(16) float ash[LL * 12];   // 24 KB, [l][k] pad to 12
    __shared__ float asum_sh[VK];
    __shared__ float red2[8][VK];
    __shared__ float scale_sh[VK];
    __shared__ int   is_last;

    const int tid  = threadIdx.x;
    const int lane = tid & 31;
    const int warp = tid >> 5;
    const int n    = blockIdx.y;

    {   // coop copy a[n] ([l][8] -> [l][12] padded), u64 granularity
        const u64* asrc = (const u64*)(g_a + (size_t)n * LL * VK);
#pragma unroll
        for (int i = tid; i < LL * 4; i += 256) {
            int l = i >> 2, kp = i & 3;
            *(u64*)(ash + l * 12 + kp * 2) = asrc[i];
        }
    }
    __syncthreads();

    const int c0 = blockIdx.x * 32 + warp * 4;

    u64 acc[4][4];
#pragma unroll
    for (int ci = 0; ci < 4; ci++)
#pragma unroll
        for (int kp = 0; kp < 4; kp++) acc[ci][kp] = 0ull;

    const float* xb = x + ((size_t)n * CC + c0) * LL;

#pragma unroll
    for (int j = 0; j < 8; j++) {
        const int lA = j * 64 + lane, lB = lA + 32;
        float4 aA0 = *(const float4*)(ash + lA * 12);
        float4 aA1 = *(const float4*)(ash + lA * 12 + 4);
        float4 aB0 = *(const float4*)(ash + lB * 12);
        float4 aB1 = *(const float4*)(ash + lB * 12 + 4);
        u64 aA[4], aB[4];
        aA[0] = pack2(aA0.x, aA0.y);  aA[1] = pack2(aA0.z, aA0.w);
        aA[2] = pack2(aA1.x, aA1.y);  aA[3] = pack2(aA1.z, aA1.w);
        aB[0] = pack2(aB0.x, aB0.y);  aB[1] = pack2(aB0.z, aB0.w);
        aB[2] = pack2(aB1.x, aB1.y);  aB[3] = pack2(aB1.z, aB1.w);
        float xA[4], xB[4];
#pragma unroll
        for (int ci = 0; ci < 4; ci++) {
            xA[ci] = xb[ci * LL + lA];
            xB[ci] = xb[ci * LL + lB];
        }
#pragma unroll
        for (int ci = 0; ci < 4; ci++) {
            u64 xdA = pack2(xA[ci], xA[ci]);
            u64 xdB = pack2(xB[ci], xB[ci]);
#pragma unroll
            for (int kp = 0; kp < 4; kp++) {
                acc[ci][kp] = ffma2(aA[kp], xdA, acc[ci][kp]);
                acc[ci][kp] = ffma2(aB[kp], xdB, acc[ci][kp]);
            }
        }
    }

    // 32 outputs per thread -> butterfly reduce-scatter: lane L keeps v[L]
    {
        float v[32];
#pragma unroll
        for (int ci = 0; ci < 4; ci++)
#pragma unroll
            for (int kp = 0; kp < 4; kp++)
                unpack2(acc[ci][kp], v[ci * 8 + 2 * kp], v[ci * 8 + 2 * kp + 1]);

#pragma unroll
        for (int o = 16; o >= 1; o >>= 1) {
            bool up = (lane & o) != 0;
#pragma unroll
            for (int i = 0; i < 32; i++) {
                if (i < o) {
                    float keep = up ? v[i + o] : v[i];
                    float send = up ? v[i] : v[i + o];
                    v[i] = keep + __shfl_xor_sync(0xffffffffu, send, o);
                }
            }
        }

        int ci = lane >> 3, k = lane & 7;
        g_axp[((size_t)n * VK + k) * CC + c0 + ci] = v[0];
    }

    // ---- arrival: 16th block for this n runs the epilogue ----
    __syncthreads();
    if (tid == 0) {
        __threadfence();
        int old = atomicAdd(&g_ctr[n], 1);
        is_last = (old == 15);
    }
    __syncthreads();
    if (!is_last) return;
    __threadfence();

    if (tid < VK) {
        float s = 0.f;
#pragma unroll
        for (int blk = 0; blk < 8; blk++)
            s += g_asum[((size_t)n * 8 + blk) * VK + tid];
        asum_sh[tid] = s;
    }
    __syncthreads();

    // residuals -> ash (reg-light cold path); thread owns c = tid, tid+256
    float sq[VK];
#pragma unroll
    for (int k = 0; k < VK; k++) {
        const float* axr = g_axp + ((size_t)n * VK + k) * CC;
        const float* cr  = centers + k * CC;
        float rA = axr[tid]       - asum_sh[k] * cr[tid];
        float rB = axr[tid + 256] - asum_sh[k] * cr[tid + 256];
        ash[k * CC + tid]       = rA;
        ash[k * CC + tid + 256] = rB;
        sq[k] = rA * rA + rB * rB;
    }

    // octet reduce-scatter within warp, then cross-warp via smem
#pragma unroll
    for (int o = 4; o >= 1; o >>= 1) {
        bool up = (lane & o) != 0;
#pragma unroll
        for (int i = 0; i < 8; i++) {
            if (i < o) {
                float keep = up ? sq[i + o] : sq[i];
                float send = up ? sq[i] : sq[i + o];
                sq[i] = keep + __shfl_xor_sync(0xffffffffu, send, o);
            }
        }
    }
    {
        float t0 = sq[0];
        t0 += __shfl_xor_sync(0xffffffffu, t0, 8);
        t0 += __shfl_xor_sync(0xffffffffu, t0, 16);
        if (lane < 8) red2[warp][lane] = t0;
    }
    __syncthreads();

    if (warp == 0) {
        int k = lane & 7;
        float ss = 0.f;
#pragma unroll
        for (int wp = 0; wp < 8; wp++) ss += red2[wp][k];
        float s1 = 1.f / fmaxf(sqrtf(ss), 1e-12f);
        float vlad = ss * s1 * s1;
        vlad += __shfl_xor_sync(0xffffffffu, vlad, 4);
        vlad += __shfl_xor_sync(0xffffffffu, vlad, 2);
        vlad += __shfl_xor_sync(0xffffffffu, vlad, 1);
        float fs = 1.f / fmaxf(sqrtf(vlad), 1e-12f);
        if (lane < 8) scale_sh[k] = s1 * fs;
    }
    __syncthreads();

#pragma unroll
    for (int k = 0; k < VK; k++) {
        float* o = out + (size_t)n * VK * CC + k * CC;
        o[tid]       = ash[k * CC + tid]       * scale_sh[k];
        o[tid + 256] = ash[k * CC + tid + 256] * scale_sh[k];
    }

    if (tid == 0) g_ctr[n] = 0;   // re-arm for next replay
}

// ---------------------------------------------------------------------------
extern "C" void kernel_launch(void* const* d_in, const int* in_sizes, int n_in,
                              void* d_out, int out_size)
{
    const float* x       = (const float*)d_in[0];  // [32,512,16,32]
    const float* conv_w  = (const float*)d_in[1];  // [10,512]
    const float* conv_b  = (const float*)d_in[2];  // [10]
    const float* centers = (const float*)d_in[3];  // [10,512]
    float* out = (float*)d_out;                    // [32, 4096]

    ka_logits_softmax <<<dim3(LL / 64, NB), 256>>>(x, conv_w, conv_b);
    kb_assign_epilogue<<<dim3(CC / 32, NB), 256>>>(x, centers, out);
}

// round 9
// speedup vs baseline: 1.5444x; 1.5444x over previous
#include <cuda_runtime.h>

#define NB   32
#define CC   512
#define LL   512
#define KG   10
#define VK   8

// Scratch (no allocations allowed)
__device__ float g_a   [NB * LL * VK];        // softmax assignments [n][l][k], k<8
__device__ float g_asum[NB * 8 * VK];         // per-l-tile assign_sum partials
__device__ float g_axp [NB * VK * CC];        // assign_x [n][k][c]
__device__ int   g_ctr [NB];                  // arrival counters (zero-init, self-resetting)

typedef unsigned long long u64;

__device__ __forceinline__ u64 pack2(float lo, float hi) {
    u64 r; asm("mov.b64 %0,{%1,%2};" : "=l"(r) : "f"(lo), "f"(hi)); return r;
}
__device__ __forceinline__ void unpack2(u64 v, float& lo, float& hi) {
    asm("mov.b64 {%0,%1},%2;" : "=f"(lo), "=f"(hi) : "l"(v));
}
__device__ __forceinline__ u64 ffma2(u64 a, u64 b, u64 c) {
    u64 d; asm("fma.rn.f32x2 %0,%1,%2,%3;" : "=l"(d) : "l"(a), "l"(b), "l"(c)); return d;
}

// ---------------------------------------------------------------------------
// KA: logits + softmax + a + assign_sum partials, fused.
// grid (L/64, N), block 256. Warp w owns c-slice [64w, 64w+64) for the
// block's 64 l's (thread = l-pair). Cross-warp combine in smem, then
// 64 threads finish softmax; writes a in [l][k] layout (2x float4/thread).
// ---------------------------------------------------------------------------
__global__ __launch_bounds__(256) void ka_logits_softmax(
    const float* __restrict__ x, const float* __restrict__ w,
    const float* __restrict__ b)
{
    __shared__ float wsh[CC * 12];        // 24 KB, [c][k] 12-padded
    __shared__ float psh[8 * KG * 64];    // 20 KB, [warp][k][l_local]
    __shared__ float red[2][VK];

    const int tid   = threadIdx.x;
    const int lane  = tid & 31;
    const int warp  = tid >> 5;
    const int n     = blockIdx.y;
    const int lbase = blockIdx.x * 64;

    for (int i = tid; i < KG * CC; i += 256) {
        int k = i >> 9, c = i & (CC - 1);
        wsh[c * 12 + k] = w[i];
    }
    __syncthreads();

    u64 accA[5], accB[5];
#pragma unroll
    for (int p = 0; p < 5; p++) { accA[p] = 0ull; accB[p] = 0ull; }

    const int c0 = warp * 64;
    const float* xp = x + ((size_t)n * CC + c0) * LL + lbase + lane * 2;
#pragma unroll 1
    for (int cb = 0; cb < 64; cb += 16) {
        const float* xc = xp + (size_t)cb * LL;
        float2 xv[16];
#pragma unroll
        for (int i = 0; i < 16; i++) xv[i] = *(const float2*)(xc + i * LL);
#pragma unroll
        for (int i = 0; i < 16; i++) {
            u64 xa = pack2(xv[i].x, xv[i].x);
            u64 xb = pack2(xv[i].y, xv[i].y);
            const float* wr = wsh + (c0 + cb + i) * 12;
            u64 w0 = *(const u64*)(wr + 0);
            u64 w1 = *(const u64*)(wr + 2);
            u64 w2 = *(const u64*)(wr + 4);
            u64 w3 = *(const u64*)(wr + 6);
            u64 w4 = *(const u64*)(wr + 8);
            accA[0] = ffma2(w0, xa, accA[0]);  accB[0] = ffma2(w0, xb, accB[0]);
            accA[1] = ffma2(w1, xa, accA[1]);  accB[1] = ffma2(w1, xb, accB[1]);
            accA[2] = ffma2(w2, xa, accA[2]);  accB[2] = ffma2(w2, xb, accB[2]);
            accA[3] = ffma2(w3, xa, accA[3]);  accB[3] = ffma2(w3, xb, accB[3]);
            accA[4] = ffma2(w4, xa, accA[4]);  accB[4] = ffma2(w4, xb, accB[4]);
        }
    }

    // stash this warp's partial logits: psh[warp][k][l_local]
    {
        float lgA[KG], lgB[KG];
#pragma unroll
        for (int p = 0; p < 5; p++) {
            unpack2(accA[p], lgA[2 * p], lgA[2 * p + 1]);
            unpack2(accB[p], lgB[2 * p], lgB[2 * p + 1]);
        }
        float* pr = psh + (warp * KG) * 64 + lane * 2;
#pragma unroll
        for (int k = 0; k < KG; k++) {
            float2 v; v.x = lgA[k]; v.y = lgB[k];
            *(float2*)(pr + k * 64) = v;
        }
    }
    __syncthreads();

    // 64 threads (warps 0-1) finish: combine 8 warps, softmax, write a + asum
    if (tid < 64) {
        float lg[KG];
#pragma unroll
        for (int k = 0; k < KG; k++) lg[k] = __ldg(b + k);
#pragma unroll
        for (int wp = 0; wp < 8; wp++) {
            const float* pr = psh + (wp * KG) * 64 + tid;
#pragma unroll
            for (int k = 0; k < KG; k++) lg[k] += pr[k * 64];
        }

        float m = lg[0];
#pragma unroll
        for (int k = 1; k < KG; k++) m = fmaxf(m, lg[k]);
        float s = 0.f;
#pragma unroll
        for (int k = 0; k < KG; k++) { lg[k] = __expf(lg[k] - m); s += lg[k]; }
        float inv = 1.f / s;

#pragma unroll
        for (int k = 0; k < VK; k++) lg[k] *= inv;

        // a in [n][l][k] layout: two coalesced float4 stores
        float* ap = g_a + ((size_t)n * LL + lbase + tid) * VK;
        *(float4*)(ap)     = make_float4(lg[0], lg[1], lg[2], lg[3]);
        *(float4*)(ap + 4) = make_float4(lg[4], lg[5], lg[6], lg[7]);

        // octet reduce-scatter: lane ends with sum over its warp of lg[lane&7]
#pragma unroll
        for (int o = 4; o >= 1; o >>= 1) {
            bool up = (lane & o) != 0;
#pragma unroll
            for (int i = 0; i < 8; i++) {
                if (i < o) {
                    float keep = up ? lg[i + o] : lg[i];
                    float send = up ? lg[i] : lg[i + o];
                    lg[i] = keep + __shfl_xor_sync(0xffffffffu, send, o);
                }
            }
        }
        float t0 = lg[0];
        t0 += __shfl_xor_sync(0xffffffffu, t0, 8);
        t0 += __shfl_xor_sync(0xffffffffu, t0, 16);
        if (lane < 8) red[warp][lane] = t0;
    }
    __syncthreads();
    if (tid < VK)
        g_asum[((size_t)n * 8 + blockIdx.x) * VK + tid] = red[0][tid] + red[1][tid];
}

// ---------------------------------------------------------------------------
// KB: assign_x + (last block per n) full epilogue.
// grid (C/32, N), block 256, 3 CTAs/SM (84-reg budget, no spills).
// Warp owns 4 c over all 512 l. a-tile padded to 12 floats/row: each l's
// 8 a-values = 2x LDS.128 (conflict-free in 8-lane phases).
// acc = 16 u64 (k-pair packed). Cold epilogue staged via smem.
// ---------------------------------------------------------------------------
__global__ __launch_bounds__(256, 3) void kb_assign_epilogue(
    const float* __restrict__ x, const float* __restrict__ centers,
    float* __restrict__ out)
{
    __shared__ __align__(16) float ash[LL * 12];   // 24 KB, [l][k] pad to 12
    __shared__ float asum_sh[VK];
    __shared__ float red2[8][VK];
    __shared__ float scale_sh[VK];
    __shared__ int   is_last;

    const int tid  = threadIdx.x;
    const int lane = tid & 31;
    const int warp = tid >> 5;
    const int n    = blockIdx.y;

    {   // coop copy a[n] ([l][8] -> [l][12] padded), u64 granularity
        const u64* asrc = (const u64*)(g_a + (size_t)n * LL * VK);
#pragma unroll
        for (int i = tid; i < LL * 4; i += 256) {
            int l = i >> 2, kp = i & 3;
            *(u64*)(ash + l * 12 + kp * 2) = asrc[i];
        }
    }
    __syncthreads();

    const int c0 = blockIdx.x * 32 + warp * 4;

    u64 acc[4][4];
#pragma unroll
    for (int ci = 0; ci < 4; ci++)
#pragma unroll
        for (int kp = 0; kp < 4; kp++) acc[ci][kp] = 0ull;

    const float* xb = x + ((size_t)n * CC + c0) * LL;

#pragma unroll
    for (int j = 0; j < 8; j++) {
        const int lA = j * 64 + lane, lB = lA + 32;
        float4 aA0 = *(const float4*)(ash + lA * 12);
        float4 aA1 = *(const float4*)(ash + lA * 12 + 4);
        float4 aB0 = *(const float4*)(ash + lB * 12);
        float4 aB1 = *(const float4*)(ash + lB * 12 + 4);
        float xA[4], xB[4];
#pragma unroll
        for (int ci = 0; ci < 4; ci++) {
            xA[ci] = xb[ci * LL + lA];
            xB[ci] = xb[ci * LL + lB];
        }
        u64 aA[4], aB[4];
        aA[0] = pack2(aA0.x, aA0.y);  aA[1] = pack2(aA0.z, aA0.w);
        aA[2] = pack2(aA1.x, aA1.y);  aA[3] = pack2(aA1.z, aA1.w);
        aB[0] = pack2(aB0.x, aB0.y);  aB[1] = pack2(aB0.z, aB0.w);
        aB[2] = pack2(aB1.x, aB1.y);  aB[3] = pack2(aB1.z, aB1.w);
#pragma unroll
        for (int ci = 0; ci < 4; ci++) {
            u64 xdA = pack2(xA[ci], xA[ci]);
            u64 xdB = pack2(xB[ci], xB[ci]);
#pragma unroll
            for (int kp = 0; kp < 4; kp++) {
                acc[ci][kp] = ffma2(aA[kp], xdA, acc[ci][kp]);
                acc[ci][kp] = ffma2(aB[kp], xdB, acc[ci][kp]);
            }
        }
    }

    // 32 outputs per thread -> butterfly reduce-scatter: lane L keeps v[L]
    {
        float v[32];
#pragma unroll
        for (int ci = 0; ci < 4; ci++)
#pragma unroll
            for (int kp = 0; kp < 4; kp++)
                unpack2(acc[ci][kp], v[ci * 8 + 2 * kp], v[ci * 8 + 2 * kp + 1]);

#pragma unroll
        for (int o = 16; o >= 1; o >>= 1) {
            bool up = (lane & o) != 0;
#pragma unroll
            for (int i = 0; i < 32; i++) {
                if (i < o) {
                    float keep = up ? v[i + o] : v[i];
                    float send = up ? v[i] : v[i + o];
                    v[i] = keep + __shfl_xor_sync(0xffffffffu, send, o);
                }
            }
        }

        int ci = lane >> 3, k = lane & 7;
        g_axp[((size_t)n * VK + k) * CC + c0 + ci] = v[0];
    }

    // ---- arrival: 16th block for this n runs the epilogue ----
    __syncthreads();
    if (tid == 0) {
        __threadfence();
        int old = atomicAdd(&g_ctr[n], 1);
        is_last = (old == 15);
    }
    __syncthreads();
    if (!is_last) return;
    __threadfence();

    if (tid < VK) {
        float s = 0.f;
#pragma unroll
        for (int blk = 0; blk < 8; blk++)
            s += g_asum[((size_t)n * 8 + blk) * VK + tid];
        asum_sh[tid] = s;
    }
    __syncthreads();

    // residuals -> ash (reg-light cold path); thread owns c = tid, tid+256
    float sq[VK];
#pragma unroll
    for (int k = 0; k < VK; k++) {
        const float* axr = g_axp + ((size_t)n * VK + k) * CC;
        const float* cr  = centers + k * CC;
        float rA = axr[tid]       - asum_sh[k] * cr[tid];
        float rB = axr[tid + 256] - asum_sh[k] * cr[tid + 256];
        ash[k * CC + tid]       = rA;
        ash[k * CC + tid + 256] = rB;
        sq[k] = rA * rA + rB * rB;
    }

    // octet reduce-scatter within warp, then cross-warp via smem
#pragma unroll
    for (int o = 4; o >= 1; o >>= 1) {
        bool up = (lane & o) != 0;
#pragma unroll
        for (int i = 0; i < 8; i++) {
            if (i < o) {
                float keep = up ? sq[i + o] : sq[i];
                float send = up ? sq[i] : sq[i + o];
                sq[i] = keep + __shfl_xor_sync(0xffffffffu, send, o);
            }
        }
    }
    {
        float t0 = sq[0];
        t0 += __shfl_xor_sync(0xffffffffu, t0, 8);
        t0 += __shfl_xor_sync(0xffffffffu, t0, 16);
        if (lane < 8) red2[warp][lane] = t0;
    }
    __syncthreads();

    if (warp == 0) {
        int k = lane & 7;
        float ss = 0.f;
#pragma unroll
        for (int wp = 0; wp < 8; wp++) ss += red2[wp][k];
        float s1 = 1.f / fmaxf(sqrtf(ss), 1e-12f);
        float vlad = ss * s1 * s1;
        vlad += __shfl_xor_sync(0xffffffffu, vlad, 4);
        vlad += __shfl_xor_sync(0xffffffffu, vlad, 2);
        vlad += __shfl_xor_sync(0xffffffffu, vlad, 1);
        float fs = 1.f / fmaxf(sqrtf(vlad), 1e-12f);
        if (lane < 8) scale_sh[k] = s1 * fs;
    }
    __syncthreads();

#pragma unroll
    for (int k = 0; k < VK; k++) {
        float* o = out + (size_t)n * VK * CC + k * CC;
        o[tid]       = ash[k * CC + tid]       * scale_sh[k];
        o[tid + 256] = ash[k * CC + tid + 256] * scale_sh[k];
    }

    if (tid == 0) g_ctr[n] = 0;   // re-arm for next replay
}

// ---------------------------------------------------------------------------
extern "C" void kernel_launch(void* const* d_in, const int* in_sizes, int n_in,
                              void* d_out, int out_size)
{
    const float* x       = (const float*)d_in[0];  // [32,512,16,32]
    const float* conv_w  = (const float*)d_in[1];  // [10,512]
    const float* conv_b  = (const float*)d_in[2];  // [10]
    const float* centers = (const float*)d_in[3];  // [10,512]
    float* out = (float*)d_out;                    // [32, 4096]

    ka_logits_softmax <<<dim3(LL / 64, NB), 256>>>(x, conv_w, conv_b);
    kb_assign_epilogue<<<dim3(CC / 32, NB), 256>>>(x, centers, out);
}